// round 4
// baseline (speedup 1.0000x reference)
#include <cuda_runtime.h>

#define BB   8
#define DIMM 1024
#define TQ   2048
#define CDD  128
#define KK   1024
#define QQ   8
#define BT   (BB*TQ)   // 16384

// ---- scratch (device globals: allocation-free rule) ----
__device__ float g_resid[BB*DIMM*TQ];   // 64 MB residual
__device__ float g_h[BT*CDD];           // 8 MB projected h
__device__ int   g_idx[BT];             // argmin codes for current step
__device__ float g_e2[QQ*KK];           // ||E_k||^2 per quantizer

// ---- packed f32x2 helpers (FFMA2 path, sm_103a) ----
__device__ __forceinline__ unsigned long long pk2(float v) {
    unsigned long long r; unsigned int u = __float_as_uint(v);
    asm("mov.b64 %0, {%1, %1};" : "=l"(r) : "r"(u));
    return r;
}
__device__ __forceinline__ void fma2(unsigned long long& d,
                                     unsigned long long a, unsigned long long b) {
    asm("fma.rn.f32x2 %0, %1, %2, %0;" : "+l"(d) : "l"(a), "l"(b));
}
__device__ __forceinline__ float2 unpk2(unsigned long long v) {
    unsigned int lo, hi;
    asm("mov.b64 {%0, %1}, %2;" : "=r"(lo), "=r"(hi) : "l"(v));
    float2 f; f.x = __uint_as_float(lo); f.y = __uint_as_float(hi);
    return f;
}

// ---- init: residual = embeddings, out = 0 ----
__global__ void k_init(const float4* __restrict__ emb, float4* __restrict__ out) {
    int i = blockIdx.x * 256 + threadIdx.x;   // 4M float4
    ((float4*)g_resid)[i] = emb[i];
    out[i] = make_float4(0.f, 0.f, 0.f, 0.f);
}

// ---- per-code squared norms, all quantizers (one warp per row) ----
__global__ void k_e2(const float* __restrict__ E) {
    int row  = blockIdx.x * (blockDim.x >> 5) + (threadIdx.x >> 5);
    int lane = threadIdx.x & 31;
    if (row >= QQ * KK) return;
    const float* e = E + (long)row * CDD;
    float4 v = *(const float4*)(e + lane * 4);
    float s = v.x*v.x + v.y*v.y + v.z*v.z + v.w*v.w;
    #pragma unroll
    for (int o = 16; o; o >>= 1) s += __shfl_xor_sync(0xffffffffu, s, o);
    if (lane == 0) g_e2[row] = s;
}

// ---- kernel 1: h[bt,c] = sum_d resid[b,d,t] * W_in[q,d,c] + b_in[q,c] ----
// grid (T/64, B), block 256. tile: 64 t x 128 c, Kdim chunks of 16.
__global__ void __launch_bounds__(256) k_proj(const float* __restrict__ Win,
                                              const float* __restrict__ bin, int q) {
    __shared__ __align__(16) float As[16][64];    // [d][t]
    __shared__ __align__(16) float Bs[16][128];   // [d][c]
    int b  = blockIdx.y;
    int t0 = blockIdx.x * 64;
    const float* Wq = Win + (long)q * DIMM * CDD;
    int tid = threadIdx.x;
    int tx = tid & 15;    // c = tx*8
    int ty = tid >> 4;    // t = ty*4
    unsigned long long acc[4][4];
    #pragma unroll
    for (int j = 0; j < 4; j++)
        #pragma unroll
        for (int i = 0; i < 4; i++) acc[j][i] = 0ull;

    const float* rb = g_resid + (long)b * DIMM * TQ + t0;
    for (int d0 = 0; d0 < DIMM; d0 += 16) {
        { // As: 1024 elts, 1 float4/thread
            int l = tid * 4; int kk = l >> 6, tt = l & 63;
            *(float4*)&As[kk][tt] = *(const float4*)(rb + (long)(d0 + kk) * TQ + tt);
        }
        { // Bs: 2048 elts, 2 float4/thread
            int l = tid * 8; int kk = l >> 7, c = l & 127;
            const float* w = Wq + (long)(d0 + kk) * CDD + c;
            *(float4*)&Bs[kk][c]     = *(const float4*)w;
            *(float4*)&Bs[kk][c + 4] = *(const float4*)(w + 4);
        }
        __syncthreads();
        #pragma unroll
        for (int kk = 0; kk < 16; kk++) {
            float4 a4 = *(const float4*)&As[kk][ty * 4];
            ulonglong2 b0 = *(const ulonglong2*)&Bs[kk][tx * 8];
            ulonglong2 b1 = *(const ulonglong2*)&Bs[kk][tx * 8 + 4];
            unsigned long long p;
            p = pk2(a4.x); fma2(acc[0][0], p, b0.x); fma2(acc[0][1], p, b0.y);
                           fma2(acc[0][2], p, b1.x); fma2(acc[0][3], p, b1.y);
            p = pk2(a4.y); fma2(acc[1][0], p, b0.x); fma2(acc[1][1], p, b0.y);
                           fma2(acc[1][2], p, b1.x); fma2(acc[1][3], p, b1.y);
            p = pk2(a4.z); fma2(acc[2][0], p, b0.x); fma2(acc[2][1], p, b0.y);
                           fma2(acc[2][2], p, b1.x); fma2(acc[2][3], p, b1.y);
            p = pk2(a4.w); fma2(acc[3][0], p, b0.x); fma2(acc[3][1], p, b0.y);
                           fma2(acc[3][2], p, b1.x); fma2(acc[3][3], p, b1.y);
        }
        __syncthreads();
    }
    // epilogue
    int bt0 = b * TQ + t0;
    const float* bq = bin + q * CDD + tx * 8;
    float bv[8];
    #pragma unroll
    for (int i = 0; i < 8; i++) bv[i] = bq[i];
    #pragma unroll
    for (int j = 0; j < 4; j++) {
        float* hp = g_h + (long)(bt0 + ty * 4 + j) * CDD + tx * 8;
        float o[8];
        #pragma unroll
        for (int pp = 0; pp < 4; pp++) {
            float2 u = unpk2(acc[j][pp]);
            o[pp * 2] = u.x + bv[pp * 2]; o[pp * 2 + 1] = u.y + bv[pp * 2 + 1];
        }
        *(float4*)hp       = make_float4(o[0], o[1], o[2], o[3]);
        *(float4*)(hp + 4) = make_float4(o[4], o[5], o[6], o[7]);
    }
}

// ---- kernel 2: argmin_k ( -2 h·E_k + ||E_k||^2 ), first-min tie break ----
// grid BT/64, block 256. 64 rows/block, 64-code n-tiles, 32-c chunks.
__global__ void __launch_bounds__(256) k_dist(const float* __restrict__ E, int q) {
    __shared__ __align__(16) float hs[64][128];   // 32 KB
    __shared__ __align__(16) float Es[32][64];    // 8 KB, [c][code]; reused for reduction
    int r0  = blockIdx.x * 64;
    int tid = threadIdx.x;
    int tx = tid & 15;    // codes tx*4..+3 per n-tile
    int ty = tid >> 4;    // rows ty*4..+3
    for (int l4 = tid; l4 < 2048; l4 += 256) {
        int rr = l4 >> 5, cc = (l4 & 31) * 4;
        *(float4*)&hs[rr][cc] = *(const float4*)(g_h + (long)(r0 + rr) * CDD + cc);
    }
    __syncthreads();

    float minv[4]; int mini[4];
    #pragma unroll
    for (int j = 0; j < 4; j++) { minv[j] = 3.0e38f; mini[j] = 0; }

    const float* Eq  = E + (long)q * KK * CDD;
    const float* e2q = g_e2 + q * KK;

    for (int n0 = 0; n0 < KK; n0 += 64) {
        unsigned long long acc[4][2];
        #pragma unroll
        for (int j = 0; j < 4; j++) { acc[j][0] = 0ull; acc[j][1] = 0ull; }
        for (int c0 = 0; c0 < 128; c0 += 32) {
            __syncthreads();
            for (int l4 = tid; l4 < 512; l4 += 256) {   // transpose-load E tile
                int n = l4 >> 3; int cj = (l4 & 7) * 4;
                float4 v = *(const float4*)(Eq + (long)(n0 + n) * CDD + c0 + cj);
                Es[cj][n] = v.x; Es[cj + 1][n] = v.y; Es[cj + 2][n] = v.z; Es[cj + 3][n] = v.w;
            }
            __syncthreads();
            #pragma unroll
            for (int cc = 0; cc < 32; cc += 4) {
                ulonglong2 e0 = *(const ulonglong2*)&Es[cc][tx * 4];
                ulonglong2 e1 = *(const ulonglong2*)&Es[cc + 1][tx * 4];
                ulonglong2 e2v = *(const ulonglong2*)&Es[cc + 2][tx * 4];
                ulonglong2 e3 = *(const ulonglong2*)&Es[cc + 3][tx * 4];
                #pragma unroll
                for (int j = 0; j < 4; j++) {
                    float4 h4 = *(const float4*)&hs[ty * 4 + j][c0 + cc];
                    unsigned long long p;
                    p = pk2(h4.x); fma2(acc[j][0], p, e0.x);  fma2(acc[j][1], p, e0.y);
                    p = pk2(h4.y); fma2(acc[j][0], p, e1.x);  fma2(acc[j][1], p, e1.y);
                    p = pk2(h4.z); fma2(acc[j][0], p, e2v.x); fma2(acc[j][1], p, e2v.y);
                    p = pk2(h4.w); fma2(acc[j][0], p, e3.x);  fma2(acc[j][1], p, e3.y);
                }
            }
        }
        #pragma unroll
        for (int j = 0; j < 4; j++) {
            #pragma unroll
            for (int pp = 0; pp < 2; pp++) {
                float2 u = unpk2(acc[j][pp]);
                int k0 = n0 + tx * 4 + pp * 2;
                float d0v = e2q[k0]     - 2.0f * u.x;
                float d1v = e2q[k0 + 1] - 2.0f * u.y;
                if (d0v < minv[j]) { minv[j] = d0v; mini[j] = k0; }
                if (d1v < minv[j]) { minv[j] = d1v; mini[j] = k0 + 1; }
            }
        }
    }
    // cross-thread reduction (reuse Es storage: 4KB floats + 4KB ints)
    float (*rminv)[16] = (float(*)[16]) & Es[0][0];
    int   (*rmini)[16] = (int(*)[16])   & Es[16][0];
    __syncthreads();
    #pragma unroll
    for (int j = 0; j < 4; j++) { rminv[ty * 4 + j][tx] = minv[j]; rmini[ty * 4 + j][tx] = mini[j]; }
    __syncthreads();
    if (tid < 64) {
        float bv = rminv[tid][0]; int bi = rmini[tid][0];
        #pragma unroll
        for (int x = 1; x < 16; x++) {
            float v = rminv[tid][x]; int ii = rmini[tid][x];
            if (v < bv || (v == bv && ii < bi)) { bv = v; bi = ii; }
        }
        g_idx[r0 + tid] = bi;
    }
}

// ---- kernel 3: qv = E[idx]·W_out + b_out; resid -= qv; out += qv ----
// grid (T/64, DIM/128, B), block 256. tile: 64 t x 128 d.
__global__ void __launch_bounds__(256) k_dec(const float* __restrict__ E,
                                             const float* __restrict__ Wout,
                                             const float* __restrict__ bout,
                                             float* __restrict__ out, int q) {
    __shared__ __align__(16) float As[128][64];   // [c][t] gathered codes, 32 KB
    __shared__ __align__(16) float Bs[16][128];   // [c][d], 8 KB
    __shared__ int sidx[64];
    int t0 = blockIdx.x * 64;
    int d0 = blockIdx.y * 128;
    int b  = blockIdx.z;
    int tid = threadIdx.x;
    int tx = tid & 15;    // t = tx*4
    int ty = tid >> 4;    // d = ty*8
    int bt0 = b * TQ + t0;
    if (tid < 64) sidx[tid] = g_idx[bt0 + tid];
    __syncthreads();

    const float* Eq = E + (long)q * KK * CDD;
    for (int l4 = tid; l4 < 2048; l4 += 256) {     // gather + transpose codes
        int tt = l4 & 63; int cj = (l4 >> 6) * 4;
        float4 v = *(const float4*)(Eq + (long)sidx[tt] * CDD + cj);
        As[cj][tt] = v.x; As[cj + 1][tt] = v.y; As[cj + 2][tt] = v.z; As[cj + 3][tt] = v.w;
    }

    const float* Wq = Wout + (long)q * CDD * DIMM + d0;
    unsigned long long acc[4][4];   // [t j][d pair]
    #pragma unroll
    for (int j = 0; j < 4; j++)
        #pragma unroll
        for (int i = 0; i < 4; i++) acc[j][i] = 0ull;

    for (int c0 = 0; c0 < 128; c0 += 16) {
        __syncthreads();
        { int l = tid * 8; int cc = l >> 7, dd = l & 127;
          const float* w = Wq + (long)(c0 + cc) * DIMM + dd;
          *(float4*)&Bs[cc][dd]     = *(const float4*)w;
          *(float4*)&Bs[cc][dd + 4] = *(const float4*)(w + 4);
        }
        __syncthreads();
        #pragma unroll
        for (int cc = 0; cc < 16; cc++) {
            float4 a4 = *(const float4*)&As[c0 + cc][tx * 4];
            ulonglong2 b0 = *(const ulonglong2*)&Bs[cc][ty * 8];
            ulonglong2 b1 = *(const ulonglong2*)&Bs[cc][ty * 8 + 4];
            unsigned long long p;
            p = pk2(a4.x); fma2(acc[0][0], p, b0.x); fma2(acc[0][1], p, b0.y);
                           fma2(acc[0][2], p, b1.x); fma2(acc[0][3], p, b1.y);
            p = pk2(a4.y); fma2(acc[1][0], p, b0.x); fma2(acc[1][1], p, b0.y);
                           fma2(acc[1][2], p, b1.x); fma2(acc[1][3], p, b1.y);
            p = pk2(a4.z); fma2(acc[2][0], p, b0.x); fma2(acc[2][1], p, b0.y);
                           fma2(acc[2][2], p, b1.x); fma2(acc[2][3], p, b1.y);
            p = pk2(a4.w); fma2(acc[3][0], p, b0.x); fma2(acc[3][1], p, b0.y);
                           fma2(acc[3][2], p, b1.x); fma2(acc[3][3], p, b1.y);
        }
    }
    // epilogue: fused resid -= qv, out += qv (float4 along t)
    float vals[8][4];
    #pragma unroll
    for (int pp = 0; pp < 4; pp++)
        #pragma unroll
        for (int j = 0; j < 4; j++) {
            float2 u = unpk2(acc[j][pp]);
            vals[pp * 2][j] = u.x; vals[pp * 2 + 1][j] = u.y;
        }
    #pragma unroll
    for (int dd = 0; dd < 8; dd++) {
        int d = d0 + ty * 8 + dd;
        float bo = bout[q * DIMM + d];
        long off = ((long)b * DIMM + d) * TQ + t0 + tx * 4;
        float4 v = make_float4(vals[dd][0] + bo, vals[dd][1] + bo,
                               vals[dd][2] + bo, vals[dd][3] + bo);
        float4 r = *(const float4*)(g_resid + off);
        float4 o = *(const float4*)(out + off);
        r.x -= v.x; r.y -= v.y; r.z -= v.z; r.w -= v.w;
        o.x += v.x; o.y += v.y; o.z += v.z; o.w += v.w;
        *(float4*)(g_resid + off) = r;
        *(float4*)(out + off)     = o;
    }
}

extern "C" void kernel_launch(void* const* d_in, const int* in_sizes, int n_in,
                              void* d_out, int out_size) {
    const float* emb  = (const float*)d_in[0];
    const float* Win  = (const float*)d_in[1];
    const float* bin  = (const float*)d_in[2];
    const float* Wout = (const float*)d_in[3];
    const float* bout = (const float*)d_in[4];
    const float* E    = (const float*)d_in[5];
    float* out = (float*)d_out;

    k_init<<<(BB * DIMM * TQ) / 4 / 256, 256>>>((const float4*)emb, (float4*)out);
    k_e2<<<(QQ * KK) / 8, 256>>>(E);
    for (int q = 0; q < QQ; q++) {
        k_proj<<<dim3(TQ / 64, BB), 256>>>(Win, bin, q);
        k_dist<<<BT / 64, 256>>>(E, q);
        k_dec<<<dim3(TQ / 64, DIMM / 128, BB), 256>>>(E, Wout, bout, out, q);
    }
}

// round 6
// speedup vs baseline: 1.4528x; 1.4528x over previous
#include <cuda_runtime.h>

#define BB   8
#define DIMM 1024
#define TQ   2048
#define CDD  128
#define KK   1024
#define QQ   8
#define BT   (BB*TQ)   // 16384

// ---- scratch (device globals) ----
__device__ float g_resid[BB*DIMM*TQ];            // 64 MB residual [b][d][t]
__device__ float g_ht[CDD*BT];                   // 8 MB h transposed [c][bt]
__device__ float g_et[QQ*CDD*KK];                // 4 MB E transposed [q][c][k]
__device__ unsigned long long g_min[BT];         // packed (enc(dist)<<32 | idx)
__device__ float g_e2[QQ*KK];                    // ||E_k||^2

// ---- packed f32x2 helpers ----
static __device__ __forceinline__ unsigned long long pk2(float v) {
    unsigned long long r; unsigned int u = __float_as_uint(v);
    asm("mov.b64 %0, {%1, %1};" : "=l"(r) : "r"(u));
    return r;
}
static __device__ __forceinline__ void fma2(unsigned long long& d,
                                            unsigned long long a, unsigned long long b) {
    asm("fma.rn.f32x2 %0, %1, %2, %0;" : "+l"(d) : "l"(a), "l"(b));
}
static __device__ __forceinline__ float2 unpk2(unsigned long long v) {
    unsigned int lo, hi;
    asm("mov.b64 {%0, %1}, %2;" : "=r"(lo), "=r"(hi) : "l"(v));
    float2 f; f.x = __uint_as_float(lo); f.y = __uint_as_float(hi);
    return f;
}
static __device__ __forceinline__ void cpa16(void* s, const void* g) {
    unsigned int sa = (unsigned int)__cvta_generic_to_shared(s);
    asm volatile("cp.async.cg.shared.global [%0], [%1], 16;" :: "r"(sa), "l"(g));
}
#define CP_COMMIT asm volatile("cp.async.commit_group;")
#define CP_WAIT0  asm volatile("cp.async.wait_group 0;")
#define CP_WAIT1  asm volatile("cp.async.wait_group 1;")

// 8 scalar rows (S0,S1 float4s) x 8 packed-t (v0,v1 ulonglong2s) -> 32 FFMA2
#define FMA2_ROW(i, s) { unsigned long long p = pk2(s); \
    fma2(acc[i][0], p, v0.x); fma2(acc[i][1], p, v0.y); \
    fma2(acc[i][2], p, v1.x); fma2(acc[i][3], p, v1.y); }
#define MICRO8(S0, S1) do { \
    FMA2_ROW(0, S0.x); FMA2_ROW(1, S0.y); FMA2_ROW(2, S0.z); FMA2_ROW(3, S0.w); \
    FMA2_ROW(4, S1.x); FMA2_ROW(5, S1.y); FMA2_ROW(6, S1.z); FMA2_ROW(7, S1.w); } while (0)

// ---- init: residual = embeddings ----
__global__ void k_init(const float4* __restrict__ emb) {
    size_t i = (size_t)blockIdx.x * 256 + threadIdx.x;
    ((float4*)g_resid)[i] = emb[i];
}

// ---- finish: out = emb - resid ----
__global__ void k_finish(const float4* __restrict__ emb, float4* __restrict__ out) {
    size_t i = (size_t)blockIdx.x * 256 + threadIdx.x;
    float4 e = emb[i]; float4 r = ((const float4*)g_resid)[i];
    out[i] = make_float4(e.x - r.x, e.y - r.y, e.z - r.z, e.w - r.w);
}

// ---- per-code squared norms ----
__global__ void k_e2(const float* __restrict__ E) {
    int row  = blockIdx.x * (blockDim.x >> 5) + (threadIdx.x >> 5);
    int lane = threadIdx.x & 31;
    if (row >= QQ * KK) return;
    const float* e = E + (size_t)row * CDD;
    float4 v = *(const float4*)(e + lane * 4);
    float s = v.x*v.x + v.y*v.y + v.z*v.z + v.w*v.w;
    #pragma unroll
    for (int o = 16; o; o >>= 1) s += __shfl_xor_sync(0xffffffffu, s, o);
    if (lane == 0) g_e2[row] = s;
}

// ---- E transpose: g_et[q][c][k] = E[q][k][c] ----
__global__ void k_et(const float* __restrict__ E) {
    __shared__ float tile[32][33];
    int q = blockIdx.z, k0 = blockIdx.x * 32, c0 = blockIdx.y * 32;
    int tx = threadIdx.x & 31, ty = threadIdx.x >> 5;   // 256 thr: ty 0..7
    const float* Eq = E + (size_t)q * KK * CDD;
    #pragma unroll
    for (int i = 0; i < 4; i++)
        tile[ty + 8*i][tx] = Eq[(size_t)(k0 + ty + 8*i) * CDD + c0 + tx];
    __syncthreads();
    float* o = g_et + (size_t)q * CDD * KK;
    #pragma unroll
    for (int i = 0; i < 4; i++)
        o[(size_t)(c0 + ty + 8*i) * KK + k0 + tx] = tile[tx][ty + 8*i];
}

// ---- kernel 1: h^T[c][bt] = sum_d resid[b,d,t]*Win[d,c] + bin[c] ----
// grid (32, 8) blocks, 128 threads. tile 64t x 128c, ktile 16, micro 8t x 8c.
__global__ void __launch_bounds__(128) k_proj(const float* __restrict__ Win,
                                              const float* __restrict__ bin, int q) {
    __shared__ __align__(16) float As[2][16][64];    // [d][t] 8KB
    __shared__ __align__(16) float Bs[2][16][128];   // [d][c] 16KB
    int b = blockIdx.y, t0 = blockIdx.x * 64;
    int tid = threadIdx.x, txt = tid & 7, tyc = tid >> 3;
    int bt0 = b * TQ + t0;
    if (tid < 64) g_min[bt0 + tid] = 0xFFFFFFFFFFFFFFFFull;  // init for k_dist merge
    const float* rb = g_resid + (size_t)b * DIMM * TQ + t0;
    const float* Wq = Win + (size_t)q * DIMM * CDD;

    // stage 0
    #pragma unroll
    for (int j = 0; j < 2; j++) { int c4 = tid + j*128; int dd = c4 >> 4, tt = (c4 & 15)*4;
        cpa16(&As[0][dd][tt], rb + (size_t)dd * TQ + tt); }
    #pragma unroll
    for (int j = 0; j < 4; j++) { int c4 = tid + j*128; int dd = c4 >> 5, cc = (c4 & 31)*4;
        cpa16(&Bs[0][dd][cc], Wq + (size_t)dd * CDD + cc); }
    CP_COMMIT;

    unsigned long long acc[8][4];
    #pragma unroll
    for (int i = 0; i < 8; i++)
        #pragma unroll
        for (int j = 0; j < 4; j++) acc[i][j] = 0ull;

    int buf = 0;
    for (int kt = 0; kt < 64; kt++) {
        if (kt + 1 < 64) {
            int d0 = (kt + 1) * 16, nb = buf ^ 1;
            #pragma unroll
            for (int j = 0; j < 2; j++) { int c4 = tid + j*128; int dd = c4 >> 4, tt = (c4 & 15)*4;
                cpa16(&As[nb][dd][tt], rb + (size_t)(d0 + dd) * TQ + tt); }
            #pragma unroll
            for (int j = 0; j < 4; j++) { int c4 = tid + j*128; int dd = c4 >> 5, cc = (c4 & 31)*4;
                cpa16(&Bs[nb][dd][cc], Wq + (size_t)(d0 + dd) * CDD + cc); }
            CP_COMMIT; CP_WAIT1;
        } else { CP_WAIT0; }
        __syncthreads();
        #pragma unroll
        for (int dd = 0; dd < 16; dd++) {
            ulonglong2 v0 = *(const ulonglong2*)&As[buf][dd][txt*8];
            ulonglong2 v1 = *(const ulonglong2*)&As[buf][dd][txt*8 + 4];
            float4 w0 = *(const float4*)&Bs[buf][dd][tyc*8];
            float4 w1 = *(const float4*)&Bs[buf][dd][tyc*8 + 4];
            MICRO8(w0, w1);
        }
        __syncthreads();
        buf ^= 1;
    }
    #pragma unroll
    for (int ci = 0; ci < 8; ci++) {
        int c = tyc * 8 + ci;
        float bi = bin[q * CDD + c];
        float2 u0 = unpk2(acc[ci][0]), u1 = unpk2(acc[ci][1]);
        float2 u2 = unpk2(acc[ci][2]), u3 = unpk2(acc[ci][3]);
        float* hp = g_ht + (size_t)c * BT + bt0 + txt * 8;
        *(float4*)hp       = make_float4(u0.x + bi, u0.y + bi, u1.x + bi, u1.y + bi);
        *(float4*)(hp + 4) = make_float4(u2.x + bi, u2.y + bi, u3.x + bi, u3.y + bi);
    }
}

// ---- kernel 2: argmin_k ( e2[k] - 2 h.E_k ) with split-K over codes ----
// grid (256, 2), 128 threads. 64 rows x 512 codes per block, micro 8t x 8k.
__global__ void __launch_bounds__(128) k_dist(int q) {
    __shared__ __align__(16) float hsT[128][64];    // 32KB [c][t]
    __shared__ __align__(16) float Es[2][16][128];  // 16KB [c][k]
    __shared__ unsigned long long rp[64][16];       // 8KB reduction
    int r0 = blockIdx.x * 64;
    int nbase = blockIdx.y * 512;
    int tid = threadIdx.x, txt = tid & 7, tyk = tid >> 3;
    const float* etq = g_et + (size_t)q * CDD * KK;
    const float* e2q = g_e2 + q * KK;

    // prologue: full hsT tile + Es stage0, one group
    #pragma unroll
    for (int j = 0; j < 16; j++) { int c4 = tid + j*128; int c = c4 >> 4, tt = (c4 & 15)*4;
        cpa16(&hsT[c][tt], g_ht + (size_t)c * BT + r0 + tt); }
    #pragma unroll
    for (int j = 0; j < 4; j++) { int c4 = tid + j*128; int cc = c4 >> 5, kk = (c4 & 31)*4;
        cpa16(&Es[0][cc][kk], etq + (size_t)cc * KK + nbase + kk); }
    CP_COMMIT;

    float minv[8]; int mini[8];
    #pragma unroll
    for (int j = 0; j < 8; j++) { minv[j] = 3.0e38f; mini[j] = 0; }
    unsigned long long acc[8][4];
    int buf = 0;
    for (int s = 0; s < 32; s++) {        // 4 n-tiles x 8 c-tiles
        if (s + 1 < 32) {
            int n0n = nbase + ((s + 1) >> 3) * 128, c0n = ((s + 1) & 7) * 16, nb = buf ^ 1;
            #pragma unroll
            for (int j = 0; j < 4; j++) { int c4 = tid + j*128; int cc = c4 >> 5, kk = (c4 & 31)*4;
                cpa16(&Es[nb][cc][kk], etq + (size_t)(c0n + cc) * KK + n0n + kk); }
            CP_COMMIT; CP_WAIT1;
        } else { CP_WAIT0; }
        __syncthreads();
        if ((s & 7) == 0) {
            #pragma unroll
            for (int i = 0; i < 8; i++)
                #pragma unroll
                for (int j = 0; j < 4; j++) acc[i][j] = 0ull;
        }
        int c0 = (s & 7) * 16;
        #pragma unroll
        for (int cc = 0; cc < 16; cc++) {
            ulonglong2 v0 = *(const ulonglong2*)&hsT[c0 + cc][txt*8];
            ulonglong2 v1 = *(const ulonglong2*)&hsT[c0 + cc][txt*8 + 4];
            float4 e0 = *(const float4*)&Es[buf][cc][tyk*8];
            float4 e1 = *(const float4*)&Es[buf][cc][tyk*8 + 4];
            MICRO8(e0, e1);
        }
        if ((s & 7) == 7) {
            int n0 = nbase + (s >> 3) * 128;
            #pragma unroll
            for (int ki = 0; ki < 8; ki++) {
                int k = n0 + tyk * 8 + ki;
                float ev = e2q[k];
                #pragma unroll
                for (int tp = 0; tp < 4; tp++) {
                    float2 u = unpk2(acc[ki][tp]);
                    float da = ev - 2.0f * u.x;
                    float db = ev - 2.0f * u.y;
                    if (da < minv[tp*2])     { minv[tp*2]     = da; mini[tp*2]     = k; }
                    if (db < minv[tp*2 + 1]) { minv[tp*2 + 1] = db; mini[tp*2 + 1] = k; }
                }
            }
        }
        __syncthreads();
        buf ^= 1;
    }
    // order-preserving pack + reduce + global merge
    #pragma unroll
    for (int j = 0; j < 8; j++) {
        unsigned int bbits = __float_as_uint(minv[j]);
        bbits = (bbits & 0x80000000u) ? ~bbits : (bbits | 0x80000000u);
        rp[txt*8 + j][tyk] = ((unsigned long long)bbits << 32) | (unsigned int)mini[j];
    }
    __syncthreads();
    if (tid < 64) {
        unsigned long long m = rp[tid][0];
        #pragma unroll
        for (int x = 1; x < 16; x++) { unsigned long long v = rp[tid][x]; if (v < m) m = v; }
        atomicMin(&g_min[r0 + tid], m);
    }
}

// ---- kernel 3: resid[b,d,t] -= E[idx]·Wout + bout ----
// grid (32, 8, 8), 128 threads. tile 64t x 128d, ctile 16, micro 8t x 8d.
__global__ void __launch_bounds__(128) k_dec(const float* __restrict__ E,
                                             const float* __restrict__ Wout,
                                             const float* __restrict__ bout, int q) {
    __shared__ __align__(16) float AsT[128][68];    // [c][t] padded, ~34.8KB
    __shared__ __align__(16) float Bs[2][16][128];  // [c][d] 16KB
    __shared__ int sidx[64];
    int t0 = blockIdx.x * 64, d0 = blockIdx.y * 128, b = blockIdx.z;
    int tid = threadIdx.x, txt = tid & 7, tyd = tid >> 3;
    int bt0 = b * TQ + t0;
    if (tid < 64) sidx[tid] = (int)(unsigned int)(g_min[bt0 + tid] & 0xFFFFFFFFull);
    const float* Wq = Wout + (size_t)q * CDD * DIMM + d0;

    // Bs stage 0 async (overlaps gather)
    #pragma unroll
    for (int j = 0; j < 4; j++) { int c4 = tid + j*128; int cc = c4 >> 5, dd = (c4 & 31)*4;
        cpa16(&Bs[0][cc][dd], Wq + (size_t)cc * DIMM + dd); }
    CP_COMMIT;
    __syncthreads();     // sidx ready

    const float* Eq = E + (size_t)q * KK * CDD;
    for (int ch = tid; ch < 2048; ch += 128) {     // gather + transpose C
        int tt = ch >> 5, cj = (ch & 31) * 4;
        float4 v = *(const float4*)(Eq + (size_t)sidx[tt] * CDD + cj);
        AsT[cj][tt] = v.x; AsT[cj+1][tt] = v.y; AsT[cj+2][tt] = v.z; AsT[cj+3][tt] = v.w;
    }
    unsigned long long acc[8][4];
    #pragma unroll
    for (int i = 0; i < 8; i++)
        #pragma unroll
        for (int j = 0; j < 4; j++) acc[i][j] = 0ull;
    __syncthreads();     // AsT ready

    int buf = 0;
    for (int ct = 0; ct < 8; ct++) {
        if (ct + 1 < 8) {
            int c0n = (ct + 1) * 16, nb = buf ^ 1;
            #pragma unroll
            for (int j = 0; j < 4; j++) { int c4 = tid + j*128; int cc = c4 >> 5, dd = (c4 & 31)*4;
                cpa16(&Bs[nb][cc][dd], Wq + (size_t)(c0n + cc) * DIMM + dd); }
            CP_COMMIT; CP_WAIT1;
        } else { CP_WAIT0; }
        __syncthreads();
        int c0 = ct * 16;
        #pragma unroll
        for (int cc = 0; cc < 16; cc++) {
            ulonglong2 v0 = *(const ulonglong2*)&AsT[c0 + cc][txt*8];
            ulonglong2 v1 = *(const ulonglong2*)&AsT[c0 + cc][txt*8 + 4];
            float4 w0 = *(const float4*)&Bs[buf][cc][tyd*8];
            float4 w1 = *(const float4*)&Bs[buf][cc][tyd*8 + 4];
            MICRO8(w0, w1);
        }
        __syncthreads();
        buf ^= 1;
    }
    // epilogue: resid -= (qv + bout)
    #pragma unroll
    for (int di = 0; di < 8; di++) {
        int d = d0 + tyd * 8 + di;
        float bo = bout[q * DIMM + d];
        float2 u0 = unpk2(acc[di][0]), u1 = unpk2(acc[di][1]);
        float2 u2 = unpk2(acc[di][2]), u3 = unpk2(acc[di][3]);
        float* rpn = g_resid + ((size_t)b * DIMM + d) * TQ + t0 + txt * 8;
        float4 r0v = *(const float4*)rpn;
        float4 r1v = *(const float4*)(rpn + 4);
        r0v.x -= u0.x + bo; r0v.y -= u0.y + bo; r0v.z -= u1.x + bo; r0v.w -= u1.y + bo;
        r1v.x -= u2.x + bo; r1v.y -= u2.y + bo; r1v.z -= u3.x + bo; r1v.w -= u3.y + bo;
        *(float4*)rpn       = r0v;
        *(float4*)(rpn + 4) = r1v;
    }
}

extern "C" void kernel_launch(void* const* d_in, const int* in_sizes, int n_in,
                              void* d_out, int out_size) {
    const float* emb  = (const float*)d_in[0];
    const float* Win  = (const float*)d_in[1];
    const float* bin  = (const float*)d_in[2];
    const float* Wout = (const float*)d_in[3];
    const float* bout = (const float*)d_in[4];
    const float* E    = (const float*)d_in[5];
    float* out = (float*)d_out;

    k_init<<<(BB * DIMM * TQ) / 4 / 256, 256>>>((const float4*)emb);
    k_et<<<dim3(KK / 32, CDD / 32, QQ), 256>>>(E);
    k_e2<<<(QQ * KK) / 8, 256>>>(E);
    for (int q = 0; q < QQ; q++) {
        k_proj<<<dim3(TQ / 64, BB), 128>>>(Win, bin, q);
        k_dist<<<dim3(BT / 64, 2), 128>>>(q);
        k_dec<<<dim3(TQ / 64, DIMM / 128, BB), 128>>>(E, Wout, bout, q);
    }
    k_finish<<<(BB * DIMM * TQ) / 4 / 256, 256>>>((const float4*)emb, (float4*)out);
}

// round 8
// speedup vs baseline: 1.7398x; 1.1975x over previous
#include <cuda_runtime.h>

#define BB   8
#define DIMM 1024
#define TQ   2048
#define CDD  128
#define KK   1024
#define QQ   8
#define BT   (BB*TQ)   // 16384

// ---- scratch (device globals) ----
__device__ float g_resid[BB*DIMM*TQ];            // 64 MB residual [b][d][t]
__device__ float g_ht[CDD*BT];                   // 8 MB h transposed [c][bt]
__device__ float g_cT[CDD*BT];                   // 8 MB gathered codes transposed [c][bt]
__device__ float g_et[QQ*CDD*KK];                // 4 MB E transposed [q][c][k]
__device__ unsigned long long g_min[BT];         // packed (enc(dist)<<32 | idx)
__device__ float g_e2[QQ*KK];                    // ||E_k||^2

// ---- packed f32x2 helpers ----
static __device__ __forceinline__ unsigned long long pk2(float v) {
    unsigned long long r; unsigned int u = __float_as_uint(v);
    asm("mov.b64 %0, {%1, %1};" : "=l"(r) : "r"(u));
    return r;
}
static __device__ __forceinline__ void fma2(unsigned long long& d,
                                            unsigned long long a, unsigned long long b) {
    asm("fma.rn.f32x2 %0, %1, %2, %0;" : "+l"(d) : "l"(a), "l"(b));
}
static __device__ __forceinline__ float2 unpk2(unsigned long long v) {
    unsigned int lo, hi;
    asm("mov.b64 {%0, %1}, %2;" : "=r"(lo), "=r"(hi) : "l"(v));
    float2 f; f.x = __uint_as_float(lo); f.y = __uint_as_float(hi);
    return f;
}
static __device__ __forceinline__ void cpa16(void* s, const void* g) {
    unsigned int sa = (unsigned int)__cvta_generic_to_shared(s);
    asm volatile("cp.async.cg.shared.global [%0], [%1], 16;" :: "r"(sa), "l"(g));
}
#define CP_COMMIT asm volatile("cp.async.commit_group;")
#define CP_WAIT0  asm volatile("cp.async.wait_group 0;")

// 8 scalar cols (w0,w1 float4s) x 4 packed-t (v ulonglong2) -> 16 FFMA2
#define MICRO4x8(w0, w1) do { unsigned long long p; \
    p = pk2(w0.x); fma2(acc[0][0], p, v.x); fma2(acc[0][1], p, v.y); \
    p = pk2(w0.y); fma2(acc[1][0], p, v.x); fma2(acc[1][1], p, v.y); \
    p = pk2(w0.z); fma2(acc[2][0], p, v.x); fma2(acc[2][1], p, v.y); \
    p = pk2(w0.w); fma2(acc[3][0], p, v.x); fma2(acc[3][1], p, v.y); \
    p = pk2(w1.x); fma2(acc[4][0], p, v.x); fma2(acc[4][1], p, v.y); \
    p = pk2(w1.y); fma2(acc[5][0], p, v.x); fma2(acc[5][1], p, v.y); \
    p = pk2(w1.z); fma2(acc[6][0], p, v.x); fma2(acc[6][1], p, v.y); \
    p = pk2(w1.w); fma2(acc[7][0], p, v.x); fma2(acc[7][1], p, v.y); } while (0)

// 8 scalar rows x 8 packed-t (v0,v1) -> 32 FFMA2 (k_dist)
#define FMA2_ROW(i, s) { unsigned long long p = pk2(s); \
    fma2(acc[i][0], p, v0.x); fma2(acc[i][1], p, v0.y); \
    fma2(acc[i][2], p, v1.x); fma2(acc[i][3], p, v1.y); }
#define MICRO8(S0, S1) do { \
    FMA2_ROW(0, S0.x); FMA2_ROW(1, S0.y); FMA2_ROW(2, S0.z); FMA2_ROW(3, S0.w); \
    FMA2_ROW(4, S1.x); FMA2_ROW(5, S1.y); FMA2_ROW(6, S1.z); FMA2_ROW(7, S1.w); } while (0)

// ---- init / finish ----
__global__ void k_init(const float4* __restrict__ emb) {
    size_t i = (size_t)blockIdx.x * 256 + threadIdx.x;
    ((float4*)g_resid)[i] = emb[i];
}
__global__ void k_finish(const float4* __restrict__ emb, float4* __restrict__ out) {
    size_t i = (size_t)blockIdx.x * 256 + threadIdx.x;
    float4 e = emb[i]; float4 r = ((const float4*)g_resid)[i];
    out[i] = make_float4(e.x - r.x, e.y - r.y, e.z - r.z, e.w - r.w);
}

// ---- per-code squared norms ----
__global__ void k_e2(const float* __restrict__ E) {
    int row  = blockIdx.x * (blockDim.x >> 5) + (threadIdx.x >> 5);
    int lane = threadIdx.x & 31;
    if (row >= QQ * KK) return;
    const float* e = E + (size_t)row * CDD;
    float4 v = *(const float4*)(e + lane * 4);
    float s = v.x*v.x + v.y*v.y + v.z*v.z + v.w*v.w;
    #pragma unroll
    for (int o = 16; o; o >>= 1) s += __shfl_xor_sync(0xffffffffu, s, o);
    if (lane == 0) g_e2[row] = s;
}

// ---- E transpose: g_et[q][c][k] = E[q][k][c] ----
__global__ void k_et(const float* __restrict__ E) {
    __shared__ float tile[32][33];
    int q = blockIdx.z, k0 = blockIdx.x * 32, c0 = blockIdx.y * 32;
    int tx = threadIdx.x & 31, ty = threadIdx.x >> 5;
    const float* Eq = E + (size_t)q * KK * CDD;
    #pragma unroll
    for (int i = 0; i < 4; i++)
        tile[ty + 8*i][tx] = Eq[(size_t)(k0 + ty + 8*i) * CDD + c0 + tx];
    __syncthreads();
    float* o = g_et + (size_t)q * CDD * KK;
    #pragma unroll
    for (int i = 0; i < 4; i++)
        o[(size_t)(c0 + ty + 8*i) * KK + k0 + tx] = tile[tx][ty + 8*i];
}

// ---- kernel 1: h^T[c][bt] = sum_d resid[b,d,t]*Win[d,c] + bin[c] ----
// grid (64, 8), 128 thr. tile 32t x 128c, ktile 32, micro 4t x 8c.
#define PROJ_PREFETCH(bufi, d0) do { \
    _Pragma("unroll") for (int j = 0; j < 2; j++) { int c4 = tid + j*128; \
        int dd = c4 >> 3, t4 = (c4 & 7) * 4; \
        cpa16(&As[bufi][dd][t4], rb + (size_t)((d0) + dd) * TQ + t4); } \
    _Pragma("unroll") for (int j = 0; j < 8; j++) { int c4 = tid + j*128; \
        int dd = c4 >> 5, cc = (c4 & 31) * 4; \
        cpa16(&Bs[bufi][dd][cc], Wq + (size_t)((d0) + dd) * CDD + cc); } \
    CP_COMMIT; } while (0)

__global__ void __launch_bounds__(128) k_proj(const float* __restrict__ Win,
                                              const float* __restrict__ bin, int q) {
    __shared__ __align__(16) float As[2][32][32];    // 8KB
    __shared__ __align__(16) float Bs[2][32][128];   // 32KB
    int b = blockIdx.y, t0 = blockIdx.x * 32;
    int tid = threadIdx.x, txt = tid & 7, tyc = tid >> 3;
    int bt0 = b * TQ + t0;
    if (tid < 32) g_min[bt0 + tid] = 0xFFFFFFFFFFFFFFFFull;
    const float* rb = g_resid + (size_t)b * DIMM * TQ + t0;
    const float* Wq = Win + (size_t)q * DIMM * CDD;

    PROJ_PREFETCH(0, 0);
    unsigned long long acc[8][2];
    #pragma unroll
    for (int i = 0; i < 8; i++) { acc[i][0] = 0ull; acc[i][1] = 0ull; }

    int buf = 0;
    for (int kt = 0; kt < 32; kt++) {
        CP_WAIT0; __syncthreads();
        if (kt + 1 < 32) PROJ_PREFETCH(buf ^ 1, (kt + 1) * 32);
        #pragma unroll 8
        for (int dd = 0; dd < 32; dd++) {
            ulonglong2 v = *(const ulonglong2*)&As[buf][dd][txt * 4];
            float4 w0 = *(const float4*)&Bs[buf][dd][tyc * 8];
            float4 w1 = *(const float4*)&Bs[buf][dd][tyc * 8 + 4];
            MICRO4x8(w0, w1);
        }
        buf ^= 1;
    }
    #pragma unroll
    for (int ci = 0; ci < 8; ci++) {
        int c = tyc * 8 + ci;
        float bi = bin[q * CDD + c];
        float2 u0 = unpk2(acc[ci][0]), u1 = unpk2(acc[ci][1]);
        *(float4*)(g_ht + (size_t)c * BT + bt0 + txt * 4) =
            make_float4(u0.x + bi, u0.y + bi, u1.x + bi, u1.y + bi);
    }
}

// ---- kernel 2: argmin_k ( e2[k] - 2 h.E_k ), 4-way code split ----
// grid (256, 4), 128 thr. 64 rows x 256 codes per block, micro 8t x 8k.
#define ES_PREFETCH(bufi, n0, c0) do { \
    _Pragma("unroll") for (int j = 0; j < 4; j++) { int c4 = tid + j*128; \
        int cc = c4 >> 5, kk = (c4 & 31) * 4; \
        cpa16(&Es[bufi][cc][kk], etq + (size_t)((c0) + cc) * KK + (n0) + kk); } \
    CP_COMMIT; } while (0)

__global__ void __launch_bounds__(128) k_dist(int q) {
    __shared__ __align__(16) float hsT[128][64];    // 32KB
    __shared__ __align__(16) float Es[2][16][128];  // 16KB
    __shared__ unsigned long long red[64][16];      // 8KB
    int r0 = blockIdx.x * 64, nbase = blockIdx.y * 256;
    int tid = threadIdx.x, txt = tid & 7, tyk = tid >> 3;
    const float* etq = g_et + (size_t)q * CDD * KK;
    const float* e2q = g_e2 + q * KK;

    float e2r[2][8];
    #pragma unroll
    for (int nt = 0; nt < 2; nt++) {
        float4 a = *(const float4*)(e2q + nbase + nt * 128 + tyk * 8);
        float4 c = *(const float4*)(e2q + nbase + nt * 128 + tyk * 8 + 4);
        e2r[nt][0] = a.x; e2r[nt][1] = a.y; e2r[nt][2] = a.z; e2r[nt][3] = a.w;
        e2r[nt][4] = c.x; e2r[nt][5] = c.y; e2r[nt][6] = c.z; e2r[nt][7] = c.w;
    }
    #pragma unroll
    for (int j = 0; j < 16; j++) { int c4 = tid + j*128; int c = c4 >> 4, t4 = (c4 & 15) * 4;
        cpa16(&hsT[c][t4], g_ht + (size_t)c * BT + r0 + t4); }
    ES_PREFETCH(0, nbase, 0);

    float minv[8]; int mini[8];
    #pragma unroll
    for (int j = 0; j < 8; j++) { minv[j] = 3.0e38f; mini[j] = 0; }
    unsigned long long acc[8][4];
    int buf = 0;
    for (int s = 0; s < 16; s++) {      // 2 n-tiles x 8 c-chunks
        CP_WAIT0; __syncthreads();
        if (s + 1 < 16) { int s1 = s + 1;
            ES_PREFETCH(buf ^ 1, nbase + (s1 >> 3) * 128, (s1 & 7) * 16); }
        if ((s & 7) == 0) {
            #pragma unroll
            for (int i = 0; i < 8; i++)
                #pragma unroll
                for (int j = 0; j < 4; j++) acc[i][j] = 0ull;
        }
        int c0 = (s & 7) * 16;
        #pragma unroll 8
        for (int cc = 0; cc < 16; cc++) {
            ulonglong2 v0 = *(const ulonglong2*)&hsT[c0 + cc][txt * 8];
            ulonglong2 v1 = *(const ulonglong2*)&hsT[c0 + cc][txt * 8 + 4];
            float4 e0 = *(const float4*)&Es[buf][cc][tyk * 8];
            float4 e1 = *(const float4*)&Es[buf][cc][tyk * 8 + 4];
            MICRO8(e0, e1);
        }
        if ((s & 7) == 7) {
            int nt = s >> 3;
            int kb = nbase + nt * 128 + tyk * 8;
            #pragma unroll
            for (int ki = 0; ki < 8; ki++) {
                float ev = e2r[nt][ki];
                int k = kb + ki;
                #pragma unroll
                for (int tp = 0; tp < 4; tp++) {
                    float2 u = unpk2(acc[ki][tp]);
                    float da = ev - 2.0f * u.x;
                    float db = ev - 2.0f * u.y;
                    if (da < minv[tp*2])     { minv[tp*2]     = da; mini[tp*2]     = k; }
                    if (db < minv[tp*2 + 1]) { minv[tp*2 + 1] = db; mini[tp*2 + 1] = k; }
                }
            }
        }
        buf ^= 1;
    }
    #pragma unroll
    for (int j = 0; j < 8; j++) {
        unsigned int bbits = __float_as_uint(minv[j]);
        bbits = (bbits & 0x80000000u) ? ~bbits : (bbits | 0x80000000u);
        red[txt * 8 + j][tyk] = ((unsigned long long)bbits << 32) | (unsigned int)mini[j];
    }
    __syncthreads();
    if (tid < 64) {
        unsigned long long m = red[tid][0];
        #pragma unroll
        for (int x = 1; x < 16; x++) { unsigned long long v = red[tid][x]; if (v < m) m = v; }
        atomicMin(&g_min[r0 + tid], m);
    }
}

// ---- kernel 2.5: g_cT[c][bt] = E[idx[bt]][c] (one gather per step) ----
__global__ void __launch_bounds__(128) k_gather(const float* __restrict__ E, int q) {
    __shared__ float sT[128][65];
    __shared__ int sidx[64];
    int bt0 = blockIdx.x * 64;
    int tid = threadIdx.x;
    if (tid < 64) sidx[tid] = (int)(unsigned int)(g_min[bt0 + tid] & 0xFFFFFFFFull);
    __syncthreads();
    const float* Eq = E + (size_t)q * KK * CDD;
    #pragma unroll
    for (int j = 0; j < 16; j++) {
        int ch = tid + j * 128; int tt = ch >> 5, c4 = ch & 31;
        float4 v = *(const float4*)(Eq + (size_t)sidx[tt] * CDD + c4 * 4);
        sT[c4*4][tt] = v.x; sT[c4*4+1][tt] = v.y; sT[c4*4+2][tt] = v.z; sT[c4*4+3][tt] = v.w;
    }
    __syncthreads();
    #pragma unroll
    for (int j = 0; j < 16; j++) {
        int ch = tid + j * 128; int c = ch >> 4, t4 = (ch & 15) * 4;
        *(float4*)(g_cT + (size_t)c * BT + bt0 + t4) =
            make_float4(sT[c][t4], sT[c][t4+1], sT[c][t4+2], sT[c][t4+3]);
    }
}

// ---- kernel 3: resid[b,d,t] -= g_cT·Wout + bout  (pure GEMM now) ----
// grid (64, 8, 8), 128 thr. tile 32t x 128d, ktile 32 (4 stages), micro 4t x 8d.
#define DEC_PREFETCH(bufi, c0) do { \
    _Pragma("unroll") for (int j = 0; j < 2; j++) { int c4 = tid + j*128; \
        int dd = c4 >> 3, t4 = (c4 & 7) * 4; \
        cpa16(&As[bufi][dd][t4], g_cT + (size_t)((c0) + dd) * BT + bt0 + t4); } \
    _Pragma("unroll") for (int j = 0; j < 8; j++) { int c4 = tid + j*128; \
        int dd = c4 >> 5, cc = (c4 & 31) * 4; \
        cpa16(&Bs[bufi][dd][cc], Wq + (size_t)((c0) + dd) * DIMM + cc); } \
    CP_COMMIT; } while (0)

__global__ void __launch_bounds__(128) k_dec(const float* __restrict__ Wout,
                                             const float* __restrict__ bout, int q) {
    __shared__ __align__(16) float As[2][32][32];    // 8KB
    __shared__ __align__(16) float Bs[2][32][128];   // 32KB
    int t0 = blockIdx.x * 32, d0 = blockIdx.y * 128, b = blockIdx.z;
    int tid = threadIdx.x, txt = tid & 7, tyc = tid >> 3;
    int bt0 = b * TQ + t0;
    const float* Wq = Wout + (size_t)q * CDD * DIMM + d0;

    DEC_PREFETCH(0, 0);
    unsigned long long acc[8][2];
    #pragma unroll
    for (int i = 0; i < 8; i++) { acc[i][0] = 0ull; acc[i][1] = 0ull; }

    int buf = 0;
    for (int kt = 0; kt < 4; kt++) {
        CP_WAIT0; __syncthreads();
        if (kt + 1 < 4) DEC_PREFETCH(buf ^ 1, (kt + 1) * 32);
        #pragma unroll 8
        for (int dd = 0; dd < 32; dd++) {
            ulonglong2 v = *(const ulonglong2*)&As[buf][dd][txt * 4];
            float4 w0 = *(const float4*)&Bs[buf][dd][tyc * 8];
            float4 w1 = *(const float4*)&Bs[buf][dd][tyc * 8 + 4];
            MICRO4x8(w0, w1);
        }
        buf ^= 1;
    }
    #pragma unroll
    for (int ci = 0; ci < 8; ci++) {
        int d = d0 + tyc * 8 + ci;
        float bo = bout[q * DIMM + d];
        float2 u0 = unpk2(acc[ci][0]), u1 = unpk2(acc[ci][1]);
        float* rp_ = g_resid + ((size_t)b * DIMM + d) * TQ + t0 + txt * 4;
        float4 r = *(const float4*)rp_;
        r.x -= u0.x + bo; r.y -= u0.y + bo; r.z -= u1.x + bo; r.w -= u1.y + bo;
        *(float4*)rp_ = r;
    }
}

extern "C" void kernel_launch(void* const* d_in, const int* in_sizes, int n_in,
                              void* d_out, int out_size) {
    const float* emb  = (const float*)d_in[0];
    const float* Win  = (const float*)d_in[1];
    const float* bin  = (const float*)d_in[2];
    const float* Wout = (const float*)d_in[3];
    const float* bout = (const float*)d_in[4];
    const float* E    = (const float*)d_in[5];
    float* out = (float*)d_out;

    k_init<<<(BB * DIMM * TQ) / 4 / 256, 256>>>((const float4*)emb);
    k_et<<<dim3(KK / 32, CDD / 32, QQ), 256>>>(E);
    k_e2<<<(QQ * KK) / 8, 256>>>(E);
    for (int q = 0; q < QQ; q++) {
        k_proj<<<dim3(TQ / 32, BB), 128>>>(Win, bin, q);
        k_dist<<<dim3(BT / 64, 4), 128>>>(q);
        k_gather<<<BT / 64, 128>>>(E, q);
        k_dec<<<dim3(TQ / 32, DIMM / 128, BB), 128>>>(Wout, bout, q);
    }
    k_finish<<<(BB * DIMM * TQ) / 4 / 256, 256>>>((const float4*)emb, (float4*)out);
}